// round 13
// baseline (speedup 1.0000x reference)
#include <cuda_runtime.h>
#include <cstdint>

#define SEQ 2048
#define DK  128

// ---------------- static device scratch (no allocations allowed) ------------
__device__ float  g_Pqk[(size_t)SEQ * SEQ];   // P_qk[i][l] = q_i . k_l
__device__ float  g_Pvv[(size_t)SEQ * SEQ];   // P_vv[i][l] = v_i . v_l
__device__ float  g_U[(size_t)SEQ * DK];      // u_l = Sqq_l k_l (incl 1/(l+1))
// per-step chain constants, 4 float4 per step:
// [0]={s_l, kqq_l, vv_l, 1/(l+1)}  [1]={k1q,k2q,k3q, l/(l+1)}
// [2]={k1u,k2u,k3u,0}              [3]={w11,w12,w13,0}   (w1j = v_l . v_{l-j})
__device__ float4 g_chain4[(size_t)SEQ * 4];

// ---------------- f32x2 packed helpers (sm_103a) ----------------------------
__device__ __forceinline__ unsigned long long ffma2(unsigned long long a,
                                                    unsigned long long b,
                                                    unsigned long long c) {
    unsigned long long d;
    asm("fma.rn.f32x2 %0, %1, %2, %3;" : "=l"(d) : "l"(a), "l"(b), "l"(c));
    return d;
}
__device__ __forceinline__ unsigned long long fmul2(unsigned long long a,
                                                    unsigned long long b) {
    unsigned long long d;
    asm("mul.rn.f32x2 %0, %1, %2;" : "=l"(d) : "l"(a), "l"(b));
    return d;
}
__device__ __forceinline__ unsigned long long fadd2(unsigned long long a,
                                                    unsigned long long b) {
    unsigned long long d;
    asm("add.rn.f32x2 %0, %1, %2;" : "=l"(d) : "l"(a), "l"(b));
    return d;
}
__device__ __forceinline__ unsigned long long pk2(float lo, float hi) {
    unsigned long long r;
    asm("mov.b64 %0, {%1, %2};" : "=l"(r) : "f"(lo), "f"(hi));
    return r;
}
__device__ __forceinline__ float2 upk2(unsigned long long a) {
    float2 f;
    asm("mov.b64 {%0, %1}, %2;" : "=f"(f.x), "=f"(f.y) : "l"(a));
    return f;
}
__device__ __forceinline__ float dot4(float4 a, float4 b) {
    return a.x * b.x + a.y * b.y + a.z * b.z + a.w * b.w;
}

// ---------------- Phase 1a: both Gram matrices in one launch ----------------
__global__ void __launch_bounds__(256) k_gemm(const float* __restrict__ q,
                                              const float* __restrict__ kk_,
                                              const float* __restrict__ v) {
    if (blockIdx.y > blockIdx.x) return;
    const float* A; const float* B; float* C;
    if (blockIdx.z == 0) { A = q; B = kk_; C = g_Pqk; }
    else                 { A = v; B = v;   C = g_Pvv; }
    __shared__ float As[32][68];
    __shared__ float Bs[32][68];
    const int tx = threadIdx.x & 15, ty = threadIdx.x >> 4;
    const int i0 = blockIdx.y * 64, l0 = blockIdx.x * 64;
    const int t = threadIdx.x;
    const int r = t >> 2, cc = (t & 3) * 8;
    float acc[4][4] = {};
    for (int k0 = 0; k0 < DK; k0 += 32) {
        float4 a0 = *(const float4*)&A[(size_t)(i0 + r) * DK + k0 + cc];
        float4 a1 = *(const float4*)&A[(size_t)(i0 + r) * DK + k0 + cc + 4];
        float4 b0 = *(const float4*)&B[(size_t)(l0 + r) * DK + k0 + cc];
        float4 b1 = *(const float4*)&B[(size_t)(l0 + r) * DK + k0 + cc + 4];
        __syncthreads();
        As[cc + 0][r] = a0.x; As[cc + 1][r] = a0.y; As[cc + 2][r] = a0.z; As[cc + 3][r] = a0.w;
        As[cc + 4][r] = a1.x; As[cc + 5][r] = a1.y; As[cc + 6][r] = a1.z; As[cc + 7][r] = a1.w;
        Bs[cc + 0][r] = b0.x; Bs[cc + 1][r] = b0.y; Bs[cc + 2][r] = b0.z; Bs[cc + 3][r] = b0.w;
        Bs[cc + 4][r] = b1.x; Bs[cc + 5][r] = b1.y; Bs[cc + 6][r] = b1.z; Bs[cc + 7][r] = b1.w;
        __syncthreads();
#pragma unroll
        for (int kv = 0; kv < 32; kv++) {
            float4 av = *(const float4*)&As[kv][ty * 4];
            float4 bv = *(const float4*)&Bs[kv][tx * 4];
            float a[4] = {av.x, av.y, av.z, av.w};
            float b[4] = {bv.x, bv.y, bv.z, bv.w};
#pragma unroll
            for (int i = 0; i < 4; i++)
#pragma unroll
                for (int j = 0; j < 4; j++) acc[i][j] += a[i] * b[j];
        }
    }
#pragma unroll
    for (int i = 0; i < 4; i++) {
        float4 o = make_float4(acc[i][0], acc[i][1], acc[i][2], acc[i][3]);
        *(float4*)&C[(size_t)(i0 + ty * 4 + i) * SEQ + l0 + tx * 4] = o;
    }
}

// ---------------- Phase 1b: U[l][d] = (1/(l+1)) sum_{i<=l} Pqk[i][l] Q[i][d]
__global__ void __launch_bounds__(256) k_U(const float* __restrict__ Q) {
    __shared__ float sh[128][8];
    const int tid = threadIdx.x;
    const int d = tid & 127, jh = tid >> 7;
    const int l0 = blockIdx.x * 8;
    float acc[4] = {0.f, 0.f, 0.f, 0.f};
    for (int i0 = 0; i0 <= l0 + 7; i0 += 128) {
        const int r = tid >> 1, c4 = (tid & 1) * 4;
        const int irow = i0 + r;
        float4 pv = *(const float4*)&g_Pqk[(size_t)irow * SEQ + l0 + c4];
        if (irow > l0 + c4 + 0) pv.x = 0.f;
        if (irow > l0 + c4 + 1) pv.y = 0.f;
        if (irow > l0 + c4 + 2) pv.z = 0.f;
        if (irow > l0 + c4 + 3) pv.w = 0.f;
        __syncthreads();
        *(float4*)&sh[r][c4] = pv;
        __syncthreads();
#pragma unroll 8
        for (int r2 = 0; r2 < 128; r2++) {
            float qv = Q[(size_t)(i0 + r2) * DK + d];
            float4 s4 = *(const float4*)&sh[r2][jh * 4];
            acc[0] += qv * s4.x; acc[1] += qv * s4.y;
            acc[2] += qv * s4.z; acc[3] += qv * s4.w;
        }
    }
#pragma unroll
    for (int jl = 0; jl < 4; jl++) {
        const int l = l0 + jh * 4 + jl;
        g_U[(size_t)l * DK + d] = acc[jl] / (float)(l + 1);
    }
}

// ---------------- Phase 1c: per-step scalars + near-diagonal dots -----------
__global__ void __launch_bounds__(256) k_scal(const float* __restrict__ q,
                                              const float* __restrict__ kk_,
                                              const float* __restrict__ v) {
    const int tid = threadIdx.x;
    const int c = tid & 63;
    const int rq = tid >> 6;
    const int l0 = blockIdx.x * 64;
    const int l = l0 + c;
    float ss = 0.f, k2 = 0.f;
    const int ntiles = blockIdx.x + 1;
    for (int tt = 0; tt < ntiles; tt++) {
        const int ib = tt * 64 + rq * 16;
#pragma unroll 4
        for (int j = 0; j < 16; j++) {
            const int i = ib + j;
            if (i <= l) {
                float pq = g_Pqk[(size_t)i * SEQ + l];
                float pv = g_Pvv[(size_t)i * SEQ + l];
                ss += pq * pv;
                k2 += pq * pq;
            }
        }
    }
    __shared__ float rs[4][64], rk[4][64];
    rs[rq][c] = ss; rk[rq][c] = k2;
    __syncthreads();
    if (tid < 64) {
        float s  = rs[0][tid] + rs[1][tid] + rs[2][tid] + rs[3][tid];
        float kq = rk[0][tid] + rk[1][tid] + rk[2][tid] + rk[3][tid];
        const int ll = l0 + tid;
        const float fl = (float)(ll + 1);
        const float bm = 1.0f / fl;
        g_chain4[(size_t)ll * 4] =
            make_float4(s * bm, kq * bm, g_Pvv[(size_t)ll * SEQ + ll], bm);
    }
    // near-diagonal dots for lags j=1..3  (4 threads per column)
    const int lc = tid >> 2, td = tid & 3;
    const int ln = l0 + lc;
    float akq[3] = {0.f, 0.f, 0.f};
    float aku[3] = {0.f, 0.f, 0.f};
    float aw[3]  = {0.f, 0.f, 0.f};
    {
        const float4* qp = (const float4*)&q[(size_t)ln * DK + td * 32];
        const float4* up = (const float4*)&g_U[(size_t)ln * DK + td * 32];
        const float4* vp = (const float4*)&v[(size_t)ln * DK + td * 32];
#pragma unroll
        for (int j = 1; j <= 3; j++) {
            if (ln >= j) {
                const float4* kp = (const float4*)&kk_[(size_t)(ln - j) * DK + td * 32];
                const float4* wp = (const float4*)&v[(size_t)(ln - j) * DK + td * 32];
#pragma unroll
                for (int x = 0; x < 8; x++) {
                    float4 a = kp[x], w4 = wp[x];
                    akq[j - 1] += dot4(a, qp[x]);
                    aku[j - 1] += dot4(a, up[x]);
                    aw[j - 1]  += dot4(w4, vp[x]);
                }
            }
        }
    }
#pragma unroll
    for (int x = 0; x < 3; x++) {
        akq[x] += __shfl_down_sync(0xffffffffu, akq[x], 2);
        akq[x] += __shfl_down_sync(0xffffffffu, akq[x], 1);
        aku[x] += __shfl_down_sync(0xffffffffu, aku[x], 2);
        aku[x] += __shfl_down_sync(0xffffffffu, aku[x], 1);
        aw[x]  += __shfl_down_sync(0xffffffffu, aw[x], 2);
        aw[x]  += __shfl_down_sync(0xffffffffu, aw[x], 1);
    }
    if (td == 0) {
        const float am = (float)ln / (float)(ln + 1);
        g_chain4[(size_t)ln * 4 + 1] = make_float4(akq[0], akq[1], akq[2], am);
        g_chain4[(size_t)ln * 4 + 2] = make_float4(aku[0], aku[1], aku[2], 0.f);
        g_chain4[(size_t)ln * 4 + 3] = make_float4(aw[0], aw[1], aw[2], 0.f);
    }
}

// ---------------- Phase 2: 2-steps-per-iteration pipelined recursion --------
// 544 threads: warps 0-15 compute (warps 1-8 also reduce: 4 per row),
// warp 16 = chain (processes 2 steps serially per iteration).
// Super-iter I: apply fused coeffs (steps 2I-4,2I-3); matvec rows 2I,2I+1 vs
// Jhat (thru 2I-3); bar; reduce both rows (6 sums each); chain does steps
// 2I-2,2I-1 correcting 2 (even) / 3 (odd) pending rank-1 updates exactly.
__global__ void __launch_bounds__(544) k_seq(const float* __restrict__ q,
                                             const float* __restrict__ kg,
                                             const float* __restrict__ v,
                                             float* __restrict__ out) {
    // vbuf: q ring4 [0,512) | u ring4 [512,1024) | k ring8 [1024,2048)
    //     | v ring8 [2048,3072)
    __shared__ float  vbuf[3072];
    __shared__ float2 part[2][2][512];
    __shared__ float4 wsumb[2][2][4][2];
    __shared__ float4 coeff[2];
    __shared__ float  sigf;

    const int tid = threadIdx.x;
    const bool is_compute = tid < 512;
    const int seg = (tid >> 7) & 3;
    const int row = tid & 127;

    const int stg_base = (seg == 0) ? 0 : (seg == 1) ? 1024 : (seg == 2) ? 2048 : 512;
    const int rmask = (seg == 1 || seg == 2) ? 7 : 3;
    const float* src = (seg == 0) ? q : (seg == 1) ? kg : (seg == 2) ? v : g_U;

    unsigned long long Jp[16];
#pragma unroll
    for (int c = 0; c < 16; c++) Jp[c] = 0ull;

    // chain state (warp 16)
    float S = 0.f, T = 0.f, trS = 0.f;
    float c1 = 0.f, c2 = 0.f, c3 = 0.f, d1 = 0.f, d2 = 0.f, d3 = 0.f;
    float sg1 = 1.f, sg2 = 1.f, sg3 = 1.f, sg4 = 1.f;
    float vv1 = 0.f, vv2 = 0.f, vv3 = 0.f, h11 = 0.f, h12 = 0.f, g11 = 0.f;
    float4 cd[8], nd[8];
#pragma unroll
    for (int x = 0; x < 8; x++) { cd[x] = make_float4(0,0,0,0); nd[x] = cd[x]; }

    for (int x = tid; x < 3072; x += 544) vbuf[x] = 0.f;
    if (tid == 0) {
        coeff[0] = make_float4(1.f, 0.f, 0.f, 0.f);
        coeff[1] = make_float4(1.f, 0.f, 0.f, 0.f);
        sigf = 1.f;
    }
    __syncthreads();
    float nxa = 0.f, nxb = 0.f;
    if (is_compute) {
        vbuf[stg_base + 0 * 128 + row] = src[row];
        vbuf[stg_base + 1 * 128 + row] = src[DK + row];
        nxa = src[2 * DK + row];
        nxb = src[3 * DK + row];
    } else {
#pragma unroll
        for (int x = 0; x < 8; x++) nd[x] = g_chain4[x];   // steps 0,1
    }
    __syncthreads();

#pragma unroll 1
    for (int I = 0; I <= SEQ / 2; I++) {
        const int buf = I & 1;

        if (is_compute) {
            // ---- (a) apply fused updates for steps 2I-4, 2I-3 --------------
            {
                float4 cc = coeff[buf];
                if (cc.x != 1.f || cc.y != 0.f || cc.z != 0.f) {
                    const int sA = (2 * I - 4) & 7, sB = (2 * I - 3) & 7;
                    const float bva = cc.y * vbuf[2048 + sA * 128 + row];
                    const float bvb = cc.z * vbuf[2048 + sB * 128 + row];
                    const unsigned long long bvap = pk2(bva, bva);
                    const unsigned long long bvbp = pk2(bvb, bvb);
                    const ulonglong2* ka = (const ulonglong2*)&vbuf[1024 + sA * 128 + seg * 32];
                    const ulonglong2* kb = (const ulonglong2*)&vbuf[1024 + sB * 128 + seg * 32];
                    if (cc.x == 1.f) {
#pragma unroll
                        for (int c = 0; c < 8; c++) {
                            ulonglong2 kva = ka[c], kvb = kb[c];
                            Jp[2 * c + 0] = ffma2(kvb.x, bvbp, ffma2(kva.x, bvap, Jp[2 * c + 0]));
                            Jp[2 * c + 1] = ffma2(kvb.y, bvbp, ffma2(kva.y, bvap, Jp[2 * c + 1]));
                        }
                    } else {
                        const unsigned long long mp = pk2(cc.x, cc.x);
#pragma unroll
                        for (int c = 0; c < 8; c++) {
                            ulonglong2 kva = ka[c], kvb = kb[c];
                            Jp[2 * c + 0] = ffma2(kvb.x, bvbp,
                                           ffma2(kva.x, bvap, fmul2(Jp[2 * c + 0], mp)));
                            Jp[2 * c + 1] = ffma2(kvb.y, bvbp,
                                           ffma2(kva.y, bvap, fmul2(Jp[2 * c + 1], mp)));
                        }
                    }
                }
            }

            // ---- (b) matvec rows 2I, 2I+1 vs Jhat --------------------------
            if (2 * I < SEQ) {
#pragma unroll
                for (int rr = 0; rr < 2; rr++) {
                    const int qslot = (2 * I + rr) & 3;
                    const ulonglong2* qp = (const ulonglong2*)&vbuf[qslot * 128 + seg * 32];
                    const ulonglong2* up = (const ulonglong2*)&vbuf[512 + qslot * 128 + seg * 32];
                    unsigned long long a1a = 0ull, a1b = 0ull, a2a = 0ull, a2b = 0ull;
#pragma unroll
                    for (int c2 = 0; c2 < 4; c2++) {
                        ulonglong2 q0 = qp[2 * c2], q1 = qp[2 * c2 + 1];
                        ulonglong2 u0 = up[2 * c2], u1 = up[2 * c2 + 1];
                        a1a = ffma2(Jp[4 * c2 + 0], q0.x, a1a);
                        a1b = ffma2(Jp[4 * c2 + 1], q0.y, a1b);
                        a1a = ffma2(Jp[4 * c2 + 2], q1.x, a1a);
                        a1b = ffma2(Jp[4 * c2 + 3], q1.y, a1b);
                        a2a = ffma2(Jp[4 * c2 + 0], u0.x, a2a);
                        a2b = ffma2(Jp[4 * c2 + 1], u0.y, a2b);
                        a2a = ffma2(Jp[4 * c2 + 2], u1.x, a2a);
                        a2b = ffma2(Jp[4 * c2 + 3], u1.y, a2b);
                    }
                    float2 f1a = upk2(a1a), f1b = upk2(a1b);
                    float2 f2a = upk2(a2a), f2b = upk2(a2b);
                    part[buf][rr][tid] = make_float2((f1a.x + f1a.y) + (f1b.x + f1b.y),
                                                     (f2a.x + f2a.y) + (f2b.x + f2b.y));
                }
            }

            // ---- (c) stage rows 2I+2, 2I+3; prefetch 2I+4, 2I+5 ------------
            if (2 * I + 2 < SEQ) {
                vbuf[stg_base + ((2 * I + 2) & rmask) * 128 + row] = nxa;
                vbuf[stg_base + ((2 * I + 3) & rmask) * 128 + row] = nxb;
            }
            nxa = (2 * I + 4 < SEQ) ? src[(size_t)(2 * I + 4) * DK + row] : 0.f;
            nxb = (2 * I + 5 < SEQ) ? src[(size_t)(2 * I + 5) * DK + row] : 0.f;

            // ---- (d) split barrier + reduce (warps 1-8) --------------------
            if (tid >= 32 && tid < 288) {
                asm volatile("bar.sync 1, 544;" ::: "memory");
                if (2 * I < SEQ) {
                    const int p = (tid >= 160) ? 1 : 0;
                    const int j = tid - 32 - p * 128;
                    const int r = 2 * I + p;
                    const unsigned long long* pp =
                        (const unsigned long long*)&part[buf][p][0];
                    unsigned long long s01 = fadd2(pp[j], pp[j + 128]);
                    unsigned long long s23 = fadd2(pp[j + 256], pp[j + 384]);
                    float2 ab = upk2(fadd2(s01, s23));
                    const float a = ab.x, b = ab.y;
                    const float vl  = vbuf[2048 + ((r    ) & 7) * 128 + j];
                    const float vm1 = vbuf[2048 + ((r - 1) & 7) * 128 + j];
                    const float vm2 = vbuf[2048 + ((r - 2) & 7) * 128 + j];
                    const float vm3 = vbuf[2048 + ((r - 3) & 7) * 128 + j];
                    float x1 = vl * a, x2 = a * a, x3 = vl * b;
                    float x4 = vm1 * a, x5 = vm2 * a, x6 = vm3 * a;
#pragma unroll
                    for (int o = 16; o > 0; o >>= 1) {
                        x1 += __shfl_down_sync(0xffffffffu, x1, o);
                        x2 += __shfl_down_sync(0xffffffffu, x2, o);
                        x3 += __shfl_down_sync(0xffffffffu, x3, o);
                        x4 += __shfl_down_sync(0xffffffffu, x4, o);
                        x5 += __shfl_down_sync(0xffffffffu, x5, o);
                        x6 += __shfl_down_sync(0xffffffffu, x6, o);
                    }
                    if ((tid & 31) == 0) {
                        const int wg = j >> 5;
                        wsumb[buf][p][wg][0] = make_float4(x1, x2, x3, x4);
                        wsumb[buf][p][wg][1] = make_float4(x5, x6, 0.f, 0.f);
                    }
                }
            } else {
                asm volatile("bar.arrive 1, 544;" ::: "memory");
            }
        } else {
            asm volatile("bar.arrive 1, 544;" ::: "memory");
            // ---- chain warp: steps 2I-2 (even, 2 pending), 2I-1 (odd, 3) ---
            if (I >= 1) {
#pragma unroll
                for (int x = 0; x < 8; x++) cd[x] = nd[x];
                if (2 * I < SEQ) {
#pragma unroll
                    for (int x = 0; x < 8; x++) nd[x] = g_chain4[(size_t)(2 * I) * 4 + x];
                }
                const int rb = 1 - buf;
                float Mm[2], Bt[2], costo[2], updo[2];
#pragma unroll
                for (int s = 0; s < 2; s++) {
                    const int l = 2 * I - 2 + s;
                    float B1 = 0.f, B2 = 0.f, B3 = 0.f, B4 = 0.f, B5 = 0.f, B6 = 0.f;
#pragma unroll
                    for (int w = 0; w < 4; w++) {
                        float4 wa = wsumb[rb][s][w][0], wb2 = wsumb[rb][s][w][1];
                        B1 += wa.x; B2 += wa.y; B3 += wa.z; B4 += wa.w;
                        B5 += wb2.x; B6 += wb2.y;
                    }
                    float4 A0 = cd[s * 4 + 0], A1c = cd[s * 4 + 1];
                    float4 A2c = cd[s * 4 + 2], A3c = cd[s * 4 + 3];
                    float Aco, C3;
                    if (s == 0) { Aco = sg3 * c1 * c2;      C3 = 0.f; }
                    else        { Aco = sg4 * c1 * c2 * c3; C3 = d3 * c2 * c1; }
                    const float C1 = d1, C2 = d2 * c1;
                    const float t1 = C1 * A1c.x, t2 = C2 * A1c.y, t3 = C3 * A1c.z;
                    const float X1 = Aco * B1 + t1 * A3c.x + t2 * A3c.y + t3 * A3c.z;
                    const float X3 = Aco * B3 + C1 * A3c.x * A2c.x
                                   + C2 * A3c.y * A2c.y + C3 * A3c.z * A2c.z;
                    const float X2 = Aco * Aco * B2
                                   + 2.f * Aco * (t1 * B4 + t2 * B5 + t3 * B6)
                                   + t1 * t1 * vv1 + t2 * t2 * vv2 + t3 * t3 * vv3
                                   + 2.f * (t1 * t2 * h11 + t1 * t3 * h12 + t2 * t3 * g11);

                    const float s_l = A0.x, kqq = A0.y, vvl = A0.z, bmv = A0.w;
                    const float amv = A1c.w;
                    trS = amv * trS + vvl * bmv;
                    const float sJ   = amv * S + bmv * X1;
                    const float A_JJ = amv * T + bmv * X2;
                    const float A_Jl = X3;
                    const float A_ll = vvl * kqq;

                    const bool first = (l == 0);
                    const float A_JJ_s = (first || A_JJ == 0.f) ? 1.f : A_JJ;
                    const float A_ll_s = (first || A_ll == 0.f) ? 1.f : A_ll;
                    const float denom  = A_JJ * A_ll - A_Jl * A_Jl;
                    const float denom_s = (first || denom == 0.f) ? 1.f : denom;

                    const float margin = s_l - A_Jl * __fdividef(sJ, A_JJ_s);
                    const float rden = __fdividef(1.f, denom_s);
                    const float wf = (A_ll * sJ - A_Jl * s_l) * rden;
                    const float wi = (A_JJ * s_l - A_Jl * sJ) * rden;
                    const float wf_c = (wi <= 0.f) ? __fdividef(sJ, A_JJ_s)
                                                   : ((wf <= 0.f) ? 0.f : wf);
                    const float wi_c = (wi <= 0.f) ? 0.f
                                                   : ((wf <= 0.f) ? __fdividef(s_l, A_ll_s) : wi);
                    const bool do_upd = margin > 0.f;

                    float cf, ci, upd;
                    if (first)       { cf = 0.f;  ci = 1.f;  upd = 1.f; S = s_l; T = A_ll; }
                    else if (do_upd) { cf = wf_c; ci = wi_c; upd = 1.f;
                                       S = cf * sJ + ci * s_l;
                                       T = cf * cf * A_JJ + 2.f * cf * ci * A_Jl
                                         + ci * ci * A_ll; }
                    else             { cf = 1.f;  ci = 0.f;  upd = 0.f; S = sJ; T = A_JJ; }

                    costo[s] = 0.5f * trS - S + 0.5f * T;
                    updo[s] = upd;

                    float m, beta, signew;
                    if (!(first || do_upd)) { m = 1.f; beta = 0.f; signew = sg1; }
                    else {
                        const float s2v = sg1 * cf;
                        if (cf == 0.f)  { m = 0.f; beta = ci; signew = 1.f; }
                        else if (fabsf(s2v) < 1e-12f || fabsf(s2v) > 1e12f)
                                        { m = s2v; beta = ci; signew = 1.f; }
                        else            { m = 1.f; beta = __fdividef(ci, s2v); signew = s2v; }
                    }
                    Mm[s] = m; Bt[s] = beta;

                    // rotate histories
                    sg4 = sg3; sg3 = sg2; sg2 = sg1; sg1 = signew;
                    c3 = c2; c2 = c1; c1 = cf;
                    d3 = d2; d2 = d1; d1 = ci;
                    vv3 = vv2; vv2 = vv1; vv1 = vvl;
                    g11 = h11; h11 = A3c.x; h12 = A3c.y;
                }
                if (tid == 512) {
                    const int lA = 2 * I - 2;
                    out[lA]     = costo[0]; out[SEQ + lA]     = updo[0];
                    out[lA + 1] = costo[1]; out[SEQ + lA + 1] = updo[1];
                    coeff[rb] = make_float4(Mm[0] * Mm[1], Mm[1] * Bt[0], Bt[1], 0.f);
                    if (lA + 1 == SEQ - 1) sigf = sg1;
                }
            }
        }
        __syncthreads();
    }

    // ---- epilogue: apply final fused update (steps 2046,2047), write J ----
    if (is_compute) {
        float4 cc = coeff[1];
        if (cc.x != 1.f || cc.y != 0.f || cc.z != 0.f) {
            const int sA = (SEQ - 2) & 7, sB = (SEQ - 1) & 7;
            const float bva = cc.y * vbuf[2048 + sA * 128 + row];
            const float bvb = cc.z * vbuf[2048 + sB * 128 + row];
            const unsigned long long bvap = pk2(bva, bva);
            const unsigned long long bvbp = pk2(bvb, bvb);
            const ulonglong2* ka = (const ulonglong2*)&vbuf[1024 + sA * 128 + seg * 32];
            const ulonglong2* kb = (const ulonglong2*)&vbuf[1024 + sB * 128 + seg * 32];
            if (cc.x == 1.f) {
#pragma unroll
                for (int c = 0; c < 8; c++) {
                    ulonglong2 kva = ka[c], kvb = kb[c];
                    Jp[2 * c + 0] = ffma2(kvb.x, bvbp, ffma2(kva.x, bvap, Jp[2 * c + 0]));
                    Jp[2 * c + 1] = ffma2(kvb.y, bvbp, ffma2(kva.y, bvap, Jp[2 * c + 1]));
                }
            } else {
                const unsigned long long mp = pk2(cc.x, cc.x);
#pragma unroll
                for (int c = 0; c < 8; c++) {
                    ulonglong2 kva = ka[c], kvb = kb[c];
                    Jp[2 * c + 0] = ffma2(kvb.x, bvbp,
                                   ffma2(kva.x, bvap, fmul2(Jp[2 * c + 0], mp)));
                    Jp[2 * c + 1] = ffma2(kvb.y, bvbp,
                                   ffma2(kva.y, bvap, fmul2(Jp[2 * c + 1], mp)));
                }
            }
        }
        const float sf = sigf;
#pragma unroll
        for (int c = 0; c < 16; c++) {
            float2 jf = upk2(Jp[c]);
            out[2 * SEQ + (size_t)row * DK + seg * 32 + 2 * c + 0] = sf * jf.x;
            out[2 * SEQ + (size_t)row * DK + seg * 32 + 2 * c + 1] = sf * jf.y;
        }
    }
}

// ---------------------------------------------------------------------------
extern "C" void kernel_launch(void* const* d_in, const int* in_sizes, int n_in,
                              void* d_out, int out_size) {
    const float* q = (const float*)d_in[0];
    const float* k = (const float*)d_in[1];
    const float* v = (const float*)d_in[2];
    float* out = (float*)d_out;

    dim3 gg(SEQ / 64, SEQ / 64, 2);
    k_gemm<<<gg, 256>>>(q, k, v);        // launch 0
    k_U<<<SEQ / 8, 256>>>(q);            // launch 1
    k_scal<<<SEQ / 64, 256>>>(q, k, v);  // launch 2
    k_seq<<<1, 544>>>(q, k, v, out);     // launch 3  <-- ncu capture slot
    (void)in_sizes; (void)n_in; (void)out_size;
}